// round 13
// baseline (speedup 1.0000x reference)
#include <cuda_runtime.h>

// Histogram2d: x[32,16384,64] f32 in [0,1) -> hist[32,128,64] * weights[128,64]
//
// Hist (mainloop/occupancy identical to the 33.2us round-12 winner):
// 512-thread blocks (2 feature-halves x 8 row-offsets), NCHUNK=13 -> 416
// blocks, single wave at occ 3 (48 warps/SM). Per-thread private u8
// histograms in SMEM, bank-aligned (lane l always hits bank l -> conflict-
// free RMWs). Dump: u16x4-in-u64 packed REDG atomicAdd into a 512KB
// per-batch accumulator (carry-free: each u16 field <= 16384 < 2^16).
// Finalize applies weights, restores the accumulator to zero for the next
// graph replay, and is launched via PDL (programmatic stream serialization)
// so its launch setup overlaps the hist tail; cudaGridDependencySynchronize
// (no early trigger upstream) preserves full completion + visibility.

constexpr int B = 32, S = 16384, F = 64, BINS = 128;
constexpr int NCHUNK = 13;             // 12*1280 + 1024 = 16384
constexpr int CHUNK = 1280;            // iters = 160/128 (<=255 u8-safe, %8==0)
constexpr int THREADS = 512;           // 16 warps: fh = w&1, soff = w>>1 (0..7)
// smem: 16 warps x 1024 words. word(w, m, l) = w*1024 + m*32 + l  (bank = l)
constexpr int SMEM_BYTES = 16 * 1024 * 4;          // 65536 B -> 3 blocks/SM (48 warps)

// u64 accumulators: word W64 = m*64 + f holds bins (4m..4m+3) of feature f:
// lo32 = bins(4m,4m+1) u16x2, hi32 = bins(4m+2,4m+3) u16x2.
constexpr int P64 = (BINS / 4) * F;                // 2048 u64 per batch
__device__ __align__(16) unsigned long long g_accum[(size_t)B * P64];  // 512 KB, starts 0

__global__ __launch_bounds__(THREADS, 3)
void hist_kernel(const float* __restrict__ x) {
    extern __shared__ unsigned int sh[];
    const int tid = threadIdx.x;
    const int w = tid >> 5, l = tid & 31;

    // zero own histogram: word (w, m, l) -> bank l, conflict-free, private
#pragma unroll
    for (int m = 0; m < 32; m++) sh[(w << 10) + (m << 5) + l] = 0u;

    unsigned char* sb = reinterpret_cast<unsigned char*>(sh);
    const unsigned int tbase = (w << 12) + (l << 2);   // byte base of this lane's hist

    const int fh = w & 1;        // feature half: 0 -> f 0..31, 1 -> f 32..63
    const int soff = w >> 1;     // row offset mod 8
    const int f = fh * 32 + l;
    const int b = blockIdx.y, c = blockIdx.x;

    const int row0 = c * CHUNK;
    const int rows = min(CHUNK, S - row0);   // 1280 or 1024
    const int iters = rows >> 3;             // 160 or 128 (%8==0) -> u8 safe
    const float* base = x + (((size_t)b * S + row0 + soff) * F + f);

    constexpr int U = 8;                     // load-ahead for MLP
#pragma unroll 1
    for (int i = 0; i < iters; i += U) {
        float v[U];
#pragma unroll
        for (int u = 0; u < U; u++)
            v[u] = __ldcs(base + (size_t)(i + u) * (8 * F));
#pragma unroll
        for (int u = 0; u < U; u++) {
            // exact trunc(v*128): RZ-add truncates mantissa; bin bits = [16:23)
            const unsigned int bits = __float_as_uint(__fadd_rz(v[u], 1.0f));
            // byte offset ((bin>>2)<<7) | (bin&3): keeps this lane in bank l
            const unsigned int off = (((bits >> 18) & 31u) << 7) | ((bits >> 16) & 3u);
            sb[tbase + off] = (unsigned char)(sb[tbase + off] + 1);
        }
    }
    __syncthreads();

    // Intra-block reduction over 8 row-offsets (dp4a byte extraction),
    // one u64 REDG per (4-bin group, feature): coalesced, fire-and-forget.
    // Per-bin block partial <= 8*160 = 1280; batch total <= 16384 < 2^16.
    unsigned long long* outp = g_accum + (size_t)b * P64;
#pragma unroll
    for (int k = 0; k < 4; k++) {
        const int u = tid + THREADS * k;     // 0..2047
        const int fo = u & 63;
        const int m  = u >> 6;               // -> bins 4m..4m+3
        const int fh2 = fo >> 5, fl = fo & 31;
        unsigned int s0 = 0, s1 = 0, s2 = 0, s3 = 0;
#pragma unroll
        for (int s = 0; s < 8; s++) {
            const unsigned int v = sh[((2 * s + fh2) << 10) + (m << 5) + fl];
            s0 = __dp4a(v, 0x00000001u, s0);
            s1 = __dp4a(v, 0x00000100u, s1);
            s2 = __dp4a(v, 0x00010000u, s2);
            s3 = __dp4a(v, 0x01000000u, s3);
        }
        const unsigned long long val =
            (unsigned long long)(s0 | (s1 << 16)) |
            ((unsigned long long)(s2 | (s3 << 16)) << 32);
        atomicAdd(&outp[m * F + fo], val);   // RED.E.ADD.64, no return
    }
}

__global__ __launch_bounds__(256)
void finalize_kernel(const float* __restrict__ wts, float* __restrict__ out) {
    // PDL: wait for hist_kernel's full completion (implicit memory flush;
    // no early trigger is used upstream, so all REDGs are visible here).
#if __CUDA_ARCH__ >= 900
    cudaGridDependencySynchronize();
#endif
    // One thread per u64 accumulator word: B*2048 = 65536 threads, 256 blocks.
    const int idx = blockIdx.x * 256 + threadIdx.x;
    const int b   = idx >> 11;
    const int W64 = idx & 2047;              // m*64 + fo
    const int m   = W64 >> 6;                // bins 4m..4m+3
    const int fo  = W64 & 63;

    uint2* pa = reinterpret_cast<uint2*>(g_accum) + idx;   // coalesced
    const uint2 v = *pa;
    *pa = make_uint2(0u, 0u);                // restore zero for next replay

    const float* wb = wts + (4 * m) * F + fo;
    float* ob = out + ((size_t)b * BINS + 4 * m) * F + fo;
    ob[0 * F] = (float)(v.x & 0xFFFFu) * wb[0 * F];
    ob[1 * F] = (float)(v.x >> 16)     * wb[1 * F];
    ob[2 * F] = (float)(v.y & 0xFFFFu) * wb[2 * F];
    ob[3 * F] = (float)(v.y >> 16)     * wb[3 * F];
}

extern "C" void kernel_launch(void* const* d_in, const int* in_sizes, int n_in,
                              void* d_out, int out_size) {
    const float* x   = (const float*)d_in[0];
    const float* wts = (const float*)d_in[1];
    float* out = (float*)d_out;

    cudaFuncSetAttribute(hist_kernel, cudaFuncAttributeMaxDynamicSharedMemorySize, SMEM_BYTES);

    dim3 grid(NCHUNK, B);   // 13 x 32 = 416 blocks, single wave at occ 3
    hist_kernel<<<grid, THREADS, SMEM_BYTES>>>(x);

    // finalize via PDL: launch setup overlaps hist tail; grid-dependency
    // sync inside the kernel enforces ordering + visibility.
    cudaLaunchConfig_t cfg = {};
    cfg.gridDim  = dim3((B * P64) / 256, 1, 1);
    cfg.blockDim = dim3(256, 1, 1);
    cfg.dynamicSmemBytes = 0;
    cfg.stream = 0;                          // legacy default stream (capture target)
    cudaLaunchAttribute attr[1];
    attr[0].id = cudaLaunchAttributeProgrammaticStreamSerialization;
    attr[0].val.programmaticStreamSerializationAllowed = 1;
    cfg.attrs = attr;
    cfg.numAttrs = 1;
    cudaError_t e = cudaLaunchKernelEx(&cfg, finalize_kernel, wts, out);
    if (e != cudaSuccess)                    // fallback: plain ordered launch
        finalize_kernel<<<(B * P64) / 256, 256>>>(wts, out);
}